// round 13
// baseline (speedup 1.0000x reference)
#include <cuda_runtime.h>
#include <cuda_bf16.h>
#include <math.h>

// ---------------- problem dims ----------------
#define BB   512
#define LL   128
#define HH   768
#define LHID 256
#define G4   1024   // 4*LHID

typedef unsigned long long ull;
typedef unsigned int u32;

// ---------------- device scratch (no allocs allowed) ----------------
__device__ float g_gatesx[(size_t)BB * LL * G4];          // 256 MB
__device__ __nv_bfloat16 g_xE  [(size_t)BB * LL * 1536];  // [ah|al]
__device__ __nv_bfloat16 g_wihE[(size_t)G4 * 1536];       // [bh|bl]
__device__ __nv_bfloat16 g_wc1E[(size_t)7 * 256 * 1536];  // per-kw [bh|bl]
__device__ __nv_bfloat16 g_whhE[(size_t)G4 * 512];        // [bh|bl] over k=256
__device__ __nv_bfloat16 g_hEA [(size_t)BB * 512];        // h hi|lo ping
__device__ __nv_bfloat16 g_hEB [(size_t)BB * 512];        // h hi|lo pong
__device__ float g_hsum[(size_t)BB * LHID];
__device__ u32   g_bar;                                   // persistent barrier
__device__ float g_y1  [(size_t)BB * 256 * 64];
__device__ float g_y2  [(size_t)BB * 64 * 32];
__device__ float g_y3  [(size_t)BB * 256 * 16];
__device__ float g_feat[(size_t)BB * 256];

// ---------------- helpers ----------------
__device__ __forceinline__ float sigf(float x) { return 1.f / (1.f + expf(-x)); }
__device__ __forceinline__ u32 smem_u32(const void* p) {
    u32 a; asm("{ .reg .u64 t; cvta.to.shared.u64 t, %1; cvt.u32.u64 %0, t; }"
               : "=r"(a) : "l"(p));
    return a;
}
__device__ __forceinline__ void cpa16(u32 dst, const void* src, bool valid) {
    asm volatile("cp.async.cg.shared.global [%0], [%1], 16, %2;"
                 :: "r"(dst), "l"(src), "r"(valid ? 16 : 0));
}
#define CPA_COMMIT() asm volatile("cp.async.commit_group;" ::: "memory")
#define CPA_WAIT0()  asm volatile("cp.async.wait_group 0;" ::: "memory")

__device__ __forceinline__ void ldmx4(u32& a0, u32& a1, u32& a2, u32& a3, u32 addr) {
    asm volatile("ldmatrix.sync.aligned.m8n8.x4.shared.b16 {%0,%1,%2,%3}, [%4];"
                 : "=r"(a0), "=r"(a1), "=r"(a2), "=r"(a3) : "r"(addr));
}
__device__ __forceinline__ void mma16816(float* d, const u32* a, const u32* b) {
    asm volatile(
        "mma.sync.aligned.m16n8k16.row.col.f32.bf16.bf16.f32 "
        "{%0,%1,%2,%3}, {%4,%5,%6,%7}, {%8,%9}, {%0,%1,%2,%3};"
        : "+f"(d[0]), "+f"(d[1]), "+f"(d[2]), "+f"(d[3])
        : "r"(a[0]), "r"(a[1]), "r"(a[2]), "r"(a[3]), "r"(b[0]), "r"(b[1]));
}

// =====================================================================
// expand: fp32 [rows,768] -> bf16 [rows,1536] as [hi block | lo block]
// =====================================================================
__global__ __launch_bounds__(256) void expand_hl(
    const float* __restrict__ src, __nv_bfloat16* __restrict__ dst, int total4)
{
    int i = blockIdx.x * 256 + threadIdx.x;
    if (i >= total4) return;
    int r = i / 192, g = i - r * 192;
    float4 v = *(const float4*)(src + (size_t)r * 768 + g * 4);
    __nv_bfloat162 h01, h23, l01, l23;
    h01.x = __float2bfloat16(v.x); h01.y = __float2bfloat16(v.y);
    h23.x = __float2bfloat16(v.z); h23.y = __float2bfloat16(v.w);
    l01.x = __float2bfloat16(v.x - __bfloat162float(h01.x));
    l01.y = __float2bfloat16(v.y - __bfloat162float(h01.y));
    l23.x = __float2bfloat16(v.z - __bfloat162float(h23.x));
    l23.y = __float2bfloat16(v.w - __bfloat162float(h23.y));
    uint2 uh, ul;
    uh.x = *(u32*)&h01; uh.y = *(u32*)&h23;
    ul.x = *(u32*)&l01; ul.y = *(u32*)&l23;
    *(uint2*)(dst + (size_t)r * 1536 + g * 4)       = uh;
    *(uint2*)(dst + (size_t)r * 1536 + 768 + g * 4) = ul;
}

// conv1 weights [256, 768, 7] -> per-kw [256, 1536] as [hi|lo]
__global__ __launch_bounds__(256) void expand_c1w(
    const float* __restrict__ w, __nv_bfloat16* __restrict__ dst)
{
    int idx = blockIdx.x * 256 + threadIdx.x;
    if (idx >= 256 * 768) return;
    int co = idx / 768, ci = idx - co * 768;
#pragma unroll
    for (int kw = 0; kw < 7; kw++) {
        float v = w[(size_t)(co * 768 + ci) * 7 + kw];
        __nv_bfloat16 h = __float2bfloat16(v);
        __nv_bfloat16 l = __float2bfloat16(v - __bfloat162float(h));
        size_t base = ((size_t)kw * 256 + co) * 1536;
        dst[base + ci]       = h;
        dst[base + 768 + ci] = l;
    }
}

// w_hh [1024, 256] -> bf16 [1024, 512] = [hi | lo]
__global__ __launch_bounds__(256) void expand_whh(
    const float* __restrict__ w, __nv_bfloat16* __restrict__ dst)
{
    int idx = blockIdx.x * 256 + threadIdx.x;
    if (idx >= 1024 * 256) return;
    int n = idx >> 8, k = idx & 255;
    float v = w[idx];
    __nv_bfloat16 h = __float2bfloat16(v);
    dst[(size_t)n * 512 + k]       = h;
    dst[(size_t)n * 512 + 256 + k] = __float2bfloat16(v - __bfloat162float(h));
}

// zero h ping buffer + barrier counter
__global__ __launch_bounds__(256) void lstm_init_kernel(__nv_bfloat16* hE)
{
    int idx = blockIdx.x * 256 + threadIdx.x;   // 512 blocks
    ((u32*)hE)[idx] = 0u;                        // 262144 u32 = all of hEA
    if (idx == 0) g_bar = 0u;
}

// =====================================================================
// HMMA GEMM: C tile 128x128, BK=64-bf16 chunks, 8 warps (4m x 2n),
// warp tile 32m x 64n. mode 0: xproj. mode 1: conv1 (7 shifted, kw-inner).
// =====================================================================
#define KP 72
#define TILEH (128 * KP)
#define SMEMB (4 * TILEH * 2)   // 73728 B

__global__ __launch_bounds__(256) void gemm_mma(
    const __nv_bfloat16* __restrict__ A,
    const __nv_bfloat16* __restrict__ Bw,
    const float* __restrict__ bias0, const float* __restrict__ bias1,
    const float* __restrict__ biasC,
    float* __restrict__ out, int mode, int nchunks)
{
    extern __shared__ __align__(16) __nv_bfloat16 sm[];
    const int tid  = threadIdx.x;
    const int lane = tid & 31;
    const int warp = tid >> 5;
    const int wm = (warp & 3) * 32;
    const int wn = (warp >> 2) * 64;
    const int m0 = blockIdx.y * 128;
    const int n0 = blockIdx.x * 128;

    float acc[2][8][4];
#pragma unroll
    for (int mf = 0; mf < 2; mf++)
#pragma unroll
        for (int j = 0; j < 8; j++)
#pragma unroll
            for (int e = 0; e < 4; e++) acc[mf][j][e] = 0.f;

    auto stage = [&](int cc, int buf) {
        int kw = 0, c = cc;
        if (mode) { kw = cc % 7; c = cc / 7; }
        int acol = (c < 12) ? c * 64 : (c < 24) ? 768 + (c - 12) * 64 : (c - 24) * 64;
        int bcol = (c < 12) ? c * 64 : (c < 24) ? (c - 12) * 64 : 768 + (c - 24) * 64;
        const __nv_bfloat16* Bp = Bw + (mode ? (size_t)kw * 256 * 1536 : (size_t)0);
        u32 abase = smem_u32(sm + (size_t)buf * 2 * TILEH);
        u32 bbase = abase + TILEH * 2;
#pragma unroll
        for (int r = 0; r < 4; r++) {
            int idx = tid + r * 256;
            int row = idx >> 3, g = idx & 7;
            bool ok = true;
            const __nv_bfloat16* src;
            if (mode) {
                int p = row + kw - 3;
                ok = (p >= 0 && p < 128);
                src = A + (size_t)(m0 + (ok ? p : 0)) * 1536 + acol + g * 8;
            } else {
                src = A + (size_t)(m0 + row) * 1536 + acol + g * 8;
            }
            cpa16(abase + (row * KP + g * 8) * 2, src, ok);
        }
#pragma unroll
        for (int r = 0; r < 4; r++) {
            int idx = tid + r * 256;
            int row = idx >> 3, g = idx & 7;
            cpa16(bbase + (row * KP + g * 8) * 2,
                  Bp + (size_t)(n0 + row) * 1536 + bcol + g * 8, true);
        }
        CPA_COMMIT();
    };

    stage(0, 0);

    for (int cc = 0; cc < nchunks; cc++) {
        const int buf = cc & 1;
        CPA_WAIT0();
        __syncthreads();
        if (cc + 1 < nchunks) stage(cc + 1, 1 - buf);

        const __nv_bfloat16* Asb = sm + (size_t)buf * 2 * TILEH;
        const __nv_bfloat16* Bsb = Asb + TILEH;
        u32 abase = smem_u32(Asb);
        u32 bbase = smem_u32(Bsb);
#pragma unroll
        for (int k16 = 0; k16 < 4; k16++) {
            const int kh = k16 * 16;
            u32 a[2][4];
#pragma unroll
            for (int mf = 0; mf < 2; mf++) {
                u32 ad = abase +
                    ((wm + 16 * mf + (lane & 15)) * KP + kh + 8 * (lane >> 4)) * 2;
                ldmx4(a[mf][0], a[mf][1], a[mf][2], a[mf][3], ad);
            }
            u32 b[8][2];
            const int quad = lane >> 3, qr = lane & 7;
#pragma unroll
            for (int jj = 0; jj < 4; jj++) {
                u32 bd = bbase +
                    ((wn + 8 * (2 * jj + (quad >> 1)) + qr) * KP + kh + 8 * (quad & 1)) * 2;
                u32 r0, r1, r2, r3;
                ldmx4(r0, r1, r2, r3, bd);
                b[2 * jj][0] = r0; b[2 * jj][1] = r1;
                b[2 * jj + 1][0] = r2; b[2 * jj + 1][1] = r3;
            }
#pragma unroll
            for (int mf = 0; mf < 2; mf++)
#pragma unroll
                for (int j = 0; j < 8; j++)
                    mma16816(acc[mf][j], a[mf], b[j]);
        }
        __syncthreads();
    }

    if (mode == 0) {
#pragma unroll
        for (int mf = 0; mf < 2; mf++) {
            int r = wm + 16 * mf + (lane >> 2);
#pragma unroll
            for (int j = 0; j < 8; j++) {
                int n = n0 + wn + 8 * j + 2 * (lane & 3);
                float bs0 = bias0[n] + bias1[n];
                float bs1 = bias0[n + 1] + bias1[n + 1];
                float2 v0 = make_float2(acc[mf][j][0] + bs0, acc[mf][j][1] + bs1);
                float2 v1 = make_float2(acc[mf][j][2] + bs0, acc[mf][j][3] + bs1);
                *(float2*)&out[(size_t)(m0 + r) * G4 + n]     = v0;
                *(float2*)&out[(size_t)(m0 + r + 8) * G4 + n] = v1;
            }
        }
    } else {
        const int b = blockIdx.y;
        float* ob = out + (size_t)b * 256 * 64;
#pragma unroll
        for (int mf = 0; mf < 2; mf++) {
            int r = wm + 16 * mf + (lane >> 2);
#pragma unroll
            for (int j = 0; j < 8; j++) {
                int co = n0 + wn + 8 * j + 2 * (lane & 3);
                float d0 = acc[mf][j][0] + biasC[co];
                float d1 = acc[mf][j][1] + biasC[co + 1];
                float d2 = acc[mf][j][2] + biasC[co];
                float d3 = acc[mf][j][3] + biasC[co + 1];
                float o0 = __shfl_xor_sync(0xffffffffu, d0, 4);
                float o1 = __shfl_xor_sync(0xffffffffu, d1, 4);
                float o2 = __shfl_xor_sync(0xffffffffu, d2, 4);
                float o3 = __shfl_xor_sync(0xffffffffu, d3, 4);
                if (!(lane & 4)) {
                    int q0 = r >> 1, q1 = (r + 8) >> 1;
                    ob[(size_t)co * 64 + q0]       = fmaxf(fmaxf(d0, o0), 0.f);
                    ob[(size_t)(co + 1) * 64 + q0] = fmaxf(fmaxf(d1, o1), 0.f);
                    ob[(size_t)co * 64 + q1]       = fmaxf(fmaxf(d2, o2), 0.f);
                    ob[(size_t)(co + 1) * 64 + q1] = fmaxf(fmaxf(d3, o3), 0.f);
                }
            }
        }
    }
}

// =====================================================================
// PERSISTENT HMMA LSTM: one launch, 64 blocks (1/SM via 195KB smem),
// block owns (b0 = by*64, j0 = bx*32) tile for all 128 steps.
// B (whhE slice, 128 rows x 512 halves) resident in smem for the whole
// kernel; A (h) staged once per step; c/hsum in registers; manual
// global barrier (monotonic atomic counter) between steps.
// smem layout (halves, pitch 520): B[0 .. 66560) A[66560 .. 99840)
// exchange overlays A region (33.3KB f32 <= 66.5KB).
// =====================================================================
#define PB 520
#define LSM_B 0
#define LSM_A (128 * PB)
#define SMLP ((128 * PB + 64 * PB) * 2)   // 199680 B
#define PE 132
#define NLBLK 64

__global__ __launch_bounds__(256) void lstm_persist(
    __nv_bfloat16* __restrict__ hA_, __nv_bfloat16* __restrict__ hB_,
    float* __restrict__ hsum,
    const __nv_bfloat16* __restrict__ whhE, const float* __restrict__ gx)
{
    extern __shared__ __align__(16) __nv_bfloat16 sm[];
    const int tid  = threadIdx.x;
    const int lane = tid & 31;
    const int warp = tid >> 5;
    const int wm = (warp & 1) * 32;         // 2 m groups (64 rows)
    const int wn = (warp >> 1) * 32;        // 4 n groups (128 cols)
    const int j0 = blockIdx.x * 32;         // 8 j tiles
    const int b0 = blockIdx.y * 64;         // 8 b tiles

    const u32 smb = smem_u32(sm);
    const u32 bB = smb + LSM_B * 2;
    const u32 bA = smb + LSM_A * 2;

    // ---- load resident B once: rows n=0..127 (n = gate*32 + jl) ----
#pragma unroll
    for (int r = 0; r < 32; r++) {
        int idx = tid + r * 256;
        int row = idx >> 6, g = idx & 63;
        int wrow = (row >> 5) * 256 + j0 + (row & 31);
        cpa16(bB + (row * PB + g * 8) * 2,
              whhE + (size_t)wrow * 512 + g * 8, true);
    }
    CPA_COMMIT();
    CPA_WAIT0();
    __syncthreads();

    // per-thread cell state (fixed tile => fixed ownership across steps)
    float creg[8], hs[8];
#pragma unroll
    for (int i = 0; i < 8; i++) { creg[i] = 0.f; hs[i] = 0.f; }

    float* sE = (float*)(sm + LSM_A);

    for (int t = 0; t < LL; t++) {
        const __nv_bfloat16* hp = (t & 1) ? hB_ : hA_;
        __nv_bfloat16*       hn = (t & 1) ? hA_ : hB_;

        // ---- stage A: 64 rows x 512 halves ----
#pragma unroll
        for (int r = 0; r < 16; r++) {
            int idx = tid + r * 256;
            int row = idx >> 6, g = idx & 63;
            cpa16(bA + (row * PB + g * 8) * 2,
                  hp + (size_t)(b0 + row) * 512 + g * 8, true);
        }
        CPA_COMMIT();

        float acc[2][4][4];
#pragma unroll
        for (int mf = 0; mf < 2; mf++)
#pragma unroll
            for (int j = 0; j < 4; j++)
#pragma unroll
                for (int e = 0; e < 4; e++) acc[mf][j][e] = 0.f;

        CPA_WAIT0();
        __syncthreads();

        // ---- 12 chunks x 4 k16, all from resident smem ----
#pragma unroll
        for (int cc = 0; cc < 12; cc++) {
            const int acol = (cc < 4) ? cc * 64 : (cc < 8) ? 256 + (cc - 4) * 64
                                                           : (cc - 8) * 64;
            const int bcol = (cc < 4) ? cc * 64 : (cc < 8) ? (cc - 4) * 64
                                                           : 256 + (cc - 8) * 64;
#pragma unroll
            for (int k16 = 0; k16 < 4; k16++) {
                const int kh = k16 * 16;
                u32 a[2][4];
#pragma unroll
                for (int mf = 0; mf < 2; mf++) {
                    u32 ad = bA +
                        ((wm + 16 * mf + (lane & 15)) * PB + acol + kh +
                         8 * (lane >> 4)) * 2;
                    ldmx4(a[mf][0], a[mf][1], a[mf][2], a[mf][3], ad);
                }
                u32 b[4][2];
                const int quad = lane >> 3, qr = lane & 7;
#pragma unroll
                for (int jj = 0; jj < 2; jj++) {
                    u32 bd = bB +
                        ((wn + 8 * (2 * jj + (quad >> 1)) + qr) * PB + bcol + kh +
                         8 * (quad & 1)) * 2;
                    u32 r0, r1, r2, r3;
                    ldmx4(r0, r1, r2, r3, bd);
                    b[2 * jj][0] = r0; b[2 * jj][1] = r1;
                    b[2 * jj + 1][0] = r2; b[2 * jj + 1][1] = r3;
                }
#pragma unroll
                for (int mf = 0; mf < 2; mf++)
#pragma unroll
                    for (int j = 0; j < 4; j++)
                        mma16816(acc[mf][j], a[mf], b[j]);
            }
        }
        __syncthreads();   // A-frags consumed; safe to overlay exchange

        // ---- exchange gates through smem ----
#pragma unroll
        for (int mf = 0; mf < 2; mf++) {
            int r = wm + 16 * mf + (lane >> 2);
#pragma unroll
            for (int j = 0; j < 4; j++) {
                int n = wn + 8 * j + 2 * (lane & 3);
                sE[r * PE + n]           = acc[mf][j][0];
                sE[r * PE + n + 1]       = acc[mf][j][1];
                sE[(r + 8) * PE + n]     = acc[mf][j][2];
                sE[(r + 8) * PE + n + 1] = acc[mf][j][3];
            }
        }
        __syncthreads();

        // ---- fused cell update (c, hsum in registers) ----
#pragma unroll
        for (int i = 0; i < 8; i++) {
            int idx = tid + i * 256;
            int bl = idx >> 5, jl = idx & 31;
            float gi = sE[bl * PE + jl];
            float gf = sE[bl * PE + 32 + jl];
            float gg = sE[bl * PE + 64 + jl];
            float go = sE[bl * PE + 96 + jl];
            int b = b0 + bl, j = j0 + jl;
            size_t gxo = ((size_t)b * LL + t) * G4 + j;
            float i_ = sigf(gi + gx[gxo]);
            float f_ = sigf(gf + gx[gxo + 256]);
            float g_ = tanhf(gg + gx[gxo + 512]);
            float o_ = sigf(go + gx[gxo + 768]);
            float cn = f_ * creg[i] + i_ * g_;
            creg[i] = cn;
            float hnv = o_ * tanhf(cn);
            hs[i] += hnv;
            __nv_bfloat16 hh = __float2bfloat16(hnv);
            hn[(size_t)b * 512 + j]       = hh;
            hn[(size_t)b * 512 + 256 + j] =
                __float2bfloat16(hnv - __bfloat162float(hh));
        }

        // ---- global barrier (monotonic counter) ----
        __threadfence();
        __syncthreads();
        if (tid == 0) {
            u32 target = (u32)(t + 1) * NLBLK;
            atomicAdd(&g_bar, 1u);
            while (atomicAdd(&g_bar, 0u) < target) __nanosleep(64);
        }
        __syncthreads();
        __threadfence();
    }

    // ---- write hsum once ----
#pragma unroll
    for (int i = 0; i < 8; i++) {
        int idx = tid + i * 256;
        int bl = idx >> 5, jl = idx & 31;
        hsum[(size_t)(b0 + bl) * LHID + j0 + jl] = hs[i];
    }
}

// =====================================================================
// conv2/3/4 + mlp (unchanged — pass)
// =====================================================================
__global__ __launch_bounds__(256) void conv2_kernel(
    const float* __restrict__ in, const float* __restrict__ w,
    const float* __restrict__ bias, float* __restrict__ out)
{
    extern __shared__ float smf[];
    float* xs = smf;
    float* ws = smf + 32 * 69;
    const int b = blockIdx.x;
    const int tid = threadIdx.x;
    const int lane = tid & 31;
    const int cog  = tid >> 5;

    float acc[8][2];
#pragma unroll
    for (int j = 0; j < 8; j++) { acc[j][0] = 0.f; acc[j][1] = 0.f; }

    const float* ib = in + (size_t)b * 256 * 64;

    for (int ci0 = 0; ci0 < 256; ci0 += 32) {
        for (int idx = tid; idx < 32 * 68; idx += 256) {
            int cil = idx / 68, s = idx - cil * 68;
            int p = s - 2;
            xs[cil * 69 + s] =
                (p >= 0 && p < 64) ? ib[(size_t)(ci0 + cil) * 64 + p] : 0.f;
        }
        for (int idx = tid; idx < 64 * 160; idx += 256) {
            int col = idx / 160, r = idx - col * 160;
            ws[idx] = w[(size_t)col * (256 * 5) + ci0 * 5 + r];
        }
        __syncthreads();

        for (int ci = 0; ci < 32; ci++) {
            const float* xr = &xs[ci * 69 + lane];
            const float* wr = &ws[cog * 160 + ci * 5];
#pragma unroll
            for (int kw = 0; kw < 5; kw++) {
                float xv0 = xr[kw];
                float xv1 = xr[kw + 32];
#pragma unroll
                for (int j = 0; j < 8; j++) {
                    float wv = wr[j * (8 * 160) + kw];
                    acc[j][0] += wv * xv0;
                    acc[j][1] += wv * xv1;
                }
            }
        }
        __syncthreads();
    }

#pragma unroll
    for (int j = 0; j < 8; j++) {
        int co = cog + 8 * j;
        float bv = bias[co];
#pragma unroll
        for (int i = 0; i < 2; i++) {
            float v = acc[j][i] + bv;
            float o = __shfl_xor_sync(0xffffffffu, v, 1);
            float m = fmaxf(v, o);
            if (!(lane & 1)) {
                int q = (lane >> 1) + 16 * i;
                out[(size_t)b * 64 * 32 + (size_t)co * 32 + q] = fmaxf(m, 0.f);
            }
        }
    }
}

__global__ __launch_bounds__(256) void conv3_kernel(
    const float* __restrict__ in, const float* __restrict__ w,
    const float* __restrict__ bias, float* __restrict__ out)
{
    extern __shared__ float smf[];
    float* xs = smf;
    float* ws = smf + 64 * 37;
    const int b   = blockIdx.x;
    const int co0 = blockIdx.y * 128;
    const int tid = threadIdx.x;
    const int lane = tid & 31;
    const int cog  = tid >> 5;

    float acc[16];
#pragma unroll
    for (int j = 0; j < 16; j++) acc[j] = 0.f;

    const float* ib = in + (size_t)b * 64 * 32;

    for (int idx = tid; idx < 64 * 34; idx += 256) {
        int cil = idx / 34, s = idx - cil * 34;
        int p = s - 1;
        xs[cil * 37 + s] = (p >= 0 && p < 32) ? ib[(size_t)cil * 32 + p] : 0.f;
    }
    for (int idx = tid; idx < 128 * 192; idx += 256) {
        int col = idx / 192, r = idx - col * 192;
        ws[idx] = w[(size_t)(co0 + col) * 192 + r];
    }
    __syncthreads();

    for (int ci = 0; ci < 64; ci++) {
        const float* xr = &xs[ci * 37 + lane];
        float xv0 = xr[0], xv1 = xr[1], xv2 = xr[2];
        const float* wr = &ws[cog * 192 + ci * 3];
#pragma unroll
        for (int j = 0; j < 16; j++) {
            const float* wj = wr + j * (8 * 192);
            acc[j] += wj[0] * xv0 + wj[1] * xv1 + wj[2] * xv2;
        }
    }

#pragma unroll
    for (int j = 0; j < 16; j++) {
        int co = co0 + cog + 8 * j;
        float v = acc[j] + bias[co];
        float o = __shfl_xor_sync(0xffffffffu, v, 1);
        float m = fmaxf(v, o);
        if (!(lane & 1)) {
            int q = lane >> 1;
            out[(size_t)b * 256 * 16 + (size_t)co * 16 + q] = fmaxf(m, 0.f);
        }
    }
}

__global__ __launch_bounds__(256) void conv4_kernel(
    const float* __restrict__ in, const float* __restrict__ w,
    const float* __restrict__ bias, float* __restrict__ out)
{
    __shared__ float xsh[4096];
    __shared__ float wsh[4096];
    int b = blockIdx.x, tid = threadIdx.x;
    const float* ib = in + (size_t)b * 4096;
    for (int i = tid; i < 4096; i += 256) { xsh[i] = ib[i]; wsh[i] = w[i]; }
    __syncthreads();
    int co = tid >> 4, p = tid & 15;
    float acc = bias[co];
#pragma unroll 8
    for (int ci = 0; ci < 256; ci++)
        acc += xsh[ci * 16 + p] * wsh[co * 256 + ci];
    out[(size_t)b * 256 + co * 16 + p] = fmaxf(acc, 0.f);
}

__global__ __launch_bounds__(128) void mlp_kernel(
    const float* __restrict__ hsum, const float* __restrict__ feat,
    const float* __restrict__ w1, const float* __restrict__ b1,
    const float* __restrict__ w2, const float* __restrict__ b2,
    const float* __restrict__ w3, const float* __restrict__ b3,
    float* __restrict__ out)
{
    __shared__ float zin[512];
    __shared__ float z1[128];
    __shared__ float z2[32];
    int b = blockIdx.x, tid = threadIdx.x;
    for (int i = tid; i < 256; i += 128) {
        zin[i]       = hsum[(size_t)b * 256 + i] * (1.f / 128.f);
        zin[256 + i] = feat[(size_t)b * 256 + i];
    }
    __syncthreads();
    {
        const float* wr = w1 + (size_t)tid * 512;
        float acc = 0.f;
#pragma unroll 4
        for (int k = 0; k < 512; k += 4) {
            float4 wv = *(const float4*)(wr + k);
            float4 xv = *(const float4*)(&zin[k]);
            acc += wv.x * xv.x + wv.y * xv.y + wv.z * xv.z + wv.w * xv.w;
        }
        z1[tid] = fmaxf(acc + b1[tid], 0.f);
    }
    __syncthreads();
    if (tid < 32) {
        const float* wr = w2 + (size_t)tid * 128;
        float acc = 0.f;
#pragma unroll
        for (int k = 0; k < 128; k += 4) {
            float4 wv = *(const float4*)(wr + k);
            float4 xv = *(const float4*)(&z1[k]);
            acc += wv.x * xv.x + wv.y * xv.y + wv.z * xv.z + wv.w * xv.w;
        }
        z2[tid] = fmaxf(acc + b2[tid], 0.f);
    }
    __syncthreads();
    if (tid < 2) {
        const float* wr = w3 + (size_t)tid * 32;
        float acc = 0.f;
#pragma unroll
        for (int k = 0; k < 32; k++) acc += wr[k] * z2[k];
        out[(size_t)b * 2 + tid] = fmaxf(acc + b3[tid], 0.f);
    }
}

// =====================================================================
// host launcher
// =====================================================================
extern "C" void kernel_launch(void* const* d_in, const int* in_sizes, int n_in,
                              void* d_out, int out_size)
{
    const float* x    = (const float*)d_in[0];
    const float* w_ih = (const float*)d_in[1];
    const float* w_hh = (const float*)d_in[2];
    const float* b_ih = (const float*)d_in[3];
    const float* b_hh = (const float*)d_in[4];
    const float* c1w  = (const float*)d_in[5];
    const float* c1b  = (const float*)d_in[6];
    const float* c2w  = (const float*)d_in[7];
    const float* c2b  = (const float*)d_in[8];
    const float* c3w  = (const float*)d_in[9];
    const float* c3b  = (const float*)d_in[10];
    const float* c4w  = (const float*)d_in[11];
    const float* c4b  = (const float*)d_in[12];
    const float* f1w  = (const float*)d_in[13];
    const float* f1b  = (const float*)d_in[14];
    const float* f2w  = (const float*)d_in[15];
    const float* f2b  = (const float*)d_in[16];
    const float* f3w  = (const float*)d_in[17];
    const float* f3b  = (const float*)d_in[18];
    float* out = (float*)d_out;

    float *gatesx, *hsum, *y1, *y2, *y3, *feat;
    __nv_bfloat16 *xE, *wihE, *wc1E, *whhE, *hEA, *hEB;
    cudaGetSymbolAddress((void**)&gatesx, g_gatesx);
    cudaGetSymbolAddress((void**)&xE,     g_xE);
    cudaGetSymbolAddress((void**)&wihE,   g_wihE);
    cudaGetSymbolAddress((void**)&wc1E,   g_wc1E);
    cudaGetSymbolAddress((void**)&whhE,   g_whhE);
    cudaGetSymbolAddress((void**)&hEA,    g_hEA);
    cudaGetSymbolAddress((void**)&hEB,    g_hEB);
    cudaGetSymbolAddress((void**)&hsum,   g_hsum);
    cudaGetSymbolAddress((void**)&y1,     g_y1);
    cudaGetSymbolAddress((void**)&y2,     g_y2);
    cudaGetSymbolAddress((void**)&y3,     g_y3);
    cudaGetSymbolAddress((void**)&feat,   g_feat);

    const int SM2 = (32 * 69 + 64 * 160) * 4;
    const int SM3 = (64 * 37 + 128 * 192) * 4;
    cudaFuncSetAttribute(conv2_kernel, cudaFuncAttributeMaxDynamicSharedMemorySize, SM2);
    cudaFuncSetAttribute(conv3_kernel, cudaFuncAttributeMaxDynamicSharedMemorySize, SM3);
    cudaFuncSetAttribute(gemm_mma, cudaFuncAttributeMaxDynamicSharedMemorySize, SMEMB);
    cudaFuncSetAttribute(lstm_persist, cudaFuncAttributeMaxDynamicSharedMemorySize, SMLP);

    // ---- bf16 hi/lo expansions ----
    expand_hl<<<(BB * LL * 192 + 255) / 256, 256>>>(x, xE, BB * LL * 192);
    expand_hl<<<(G4 * 192 + 255) / 256, 256>>>(w_ih, wihE, G4 * 192);
    expand_c1w<<<(256 * 768 + 255) / 256, 256>>>(c1w, wc1E);
    expand_whh<<<(1024 * 256 + 255) / 256, 256>>>(w_hh, whhE);

    // ---- conv1 via 7 accumulated HMMA GEMMs (kw-inner, 252 chunks) ----
    gemm_mma<<<dim3(2, BB), 256, SMEMB>>>(
        xE, wc1E, nullptr, nullptr, c1b, y1, 1, 7 * 36);

    // ---- rest of CNN ----
    conv2_kernel<<<BB, 256, SM2>>>(y1, c2w, c2b, y2);
    conv3_kernel<<<dim3(BB, 2), 256, SM3>>>(y2, c3w, c3b, y3);
    conv4_kernel<<<BB, 256>>>(y3, c4w, c4b, feat);

    // ---- input projection via HMMA (36 chunks) ----
    gemm_mma<<<dim3(G4 / 128, (BB * LL) / 128), 256, SMEMB>>>(
        xE, wihE, b_ih, b_hh, nullptr, gatesx, 0, 36);

    // ---- LSTM recurrence: ONE persistent kernel ----
    lstm_init_kernel<<<BB, 256>>>(hEA);
    lstm_persist<<<dim3(8, 8), 256, SMLP>>>(hEA, hEB, hsum, whhE, gatesx);

    // ---- MLP head ----
    mlp_kernel<<<BB, 128>>>(hsum, feat, f1w, f1b, f2w, f2b, f3w, f3b, out);
}

// round 15
// speedup vs baseline: 1.3748x; 1.3748x over previous
#include <cuda_runtime.h>
#include <cuda_bf16.h>
#include <math.h>

// ---------------- problem dims ----------------
#define BB   512
#define LL   128
#define HH   768
#define LHID 256
#define G4   1024   // 4*LHID

typedef unsigned long long ull;
typedef unsigned int u32;

// ---------------- device scratch (no allocs allowed) ----------------
__device__ float g_gatesx[(size_t)BB * LL * G4];          // 256 MB
__device__ __nv_bfloat16 g_xE  [(size_t)BB * LL * 1536];  // [ah|al]
__device__ __nv_bfloat16 g_wihE[(size_t)G4 * 1536];       // [bh|bl]
__device__ __nv_bfloat16 g_wc1E[(size_t)7 * 256 * 1536];  // per-kw [bh|bl]
__device__ __nv_bfloat16 g_whhE[(size_t)G4 * 512];        // [bh|bl] over k=256
__device__ __nv_bfloat16 g_hEA [(size_t)BB * 512];        // h hi|lo ping
__device__ __nv_bfloat16 g_hEB [(size_t)BB * 512];        // h hi|lo pong
__device__ float g_c   [(size_t)BB * LHID];
__device__ float g_hsum[(size_t)BB * LHID];
__device__ float g_y1  [(size_t)BB * 256 * 64];
__device__ float g_y2  [(size_t)BB * 64 * 32];
__device__ float g_y3  [(size_t)BB * 256 * 16];
__device__ float g_feat[(size_t)BB * 256];

// ---------------- helpers ----------------
__device__ __forceinline__ float sigf(float x) { return 1.f / (1.f + expf(-x)); }
__device__ __forceinline__ u32 smem_u32(const void* p) {
    u32 a; asm("{ .reg .u64 t; cvta.to.shared.u64 t, %1; cvt.u32.u64 %0, t; }"
               : "=r"(a) : "l"(p));
    return a;
}
__device__ __forceinline__ void cpa16(u32 dst, const void* src, bool valid) {
    asm volatile("cp.async.cg.shared.global [%0], [%1], 16, %2;"
                 :: "r"(dst), "l"(src), "r"(valid ? 16 : 0));
}
#define CPA_COMMIT() asm volatile("cp.async.commit_group;" ::: "memory")
#define CPA_WAIT0()  asm volatile("cp.async.wait_group 0;" ::: "memory")

__device__ __forceinline__ void ldmx4(u32& a0, u32& a1, u32& a2, u32& a3, u32 addr) {
    asm volatile("ldmatrix.sync.aligned.m8n8.x4.shared.b16 {%0,%1,%2,%3}, [%4];"
                 : "=r"(a0), "=r"(a1), "=r"(a2), "=r"(a3) : "r"(addr));
}
__device__ __forceinline__ void mma16816(float* d, const u32* a, const u32* b) {
    asm volatile(
        "mma.sync.aligned.m16n8k16.row.col.f32.bf16.bf16.f32 "
        "{%0,%1,%2,%3}, {%4,%5,%6,%7}, {%8,%9}, {%0,%1,%2,%3};"
        : "+f"(d[0]), "+f"(d[1]), "+f"(d[2]), "+f"(d[3])
        : "r"(a[0]), "r"(a[1]), "r"(a[2]), "r"(a[3]), "r"(b[0]), "r"(b[1]));
}

// =====================================================================
// expand: fp32 [rows,768] -> bf16 [rows,1536] as [hi block | lo block]
// =====================================================================
__global__ __launch_bounds__(256) void expand_hl(
    const float* __restrict__ src, __nv_bfloat16* __restrict__ dst, int total4)
{
    int i = blockIdx.x * 256 + threadIdx.x;
    if (i >= total4) return;
    int r = i / 192, g = i - r * 192;
    float4 v = *(const float4*)(src + (size_t)r * 768 + g * 4);
    __nv_bfloat162 h01, h23, l01, l23;
    h01.x = __float2bfloat16(v.x); h01.y = __float2bfloat16(v.y);
    h23.x = __float2bfloat16(v.z); h23.y = __float2bfloat16(v.w);
    l01.x = __float2bfloat16(v.x - __bfloat162float(h01.x));
    l01.y = __float2bfloat16(v.y - __bfloat162float(h01.y));
    l23.x = __float2bfloat16(v.z - __bfloat162float(h23.x));
    l23.y = __float2bfloat16(v.w - __bfloat162float(h23.y));
    uint2 uh, ul;
    uh.x = *(u32*)&h01; uh.y = *(u32*)&h23;
    ul.x = *(u32*)&l01; ul.y = *(u32*)&l23;
    *(uint2*)(dst + (size_t)r * 1536 + g * 4)       = uh;
    *(uint2*)(dst + (size_t)r * 1536 + 768 + g * 4) = ul;
}

// conv1 weights [256, 768, 7] -> per-kw [256, 1536] as [hi|lo]
__global__ __launch_bounds__(256) void expand_c1w(
    const float* __restrict__ w, __nv_bfloat16* __restrict__ dst)
{
    int idx = blockIdx.x * 256 + threadIdx.x;
    if (idx >= 256 * 768) return;
    int co = idx / 768, ci = idx - co * 768;
#pragma unroll
    for (int kw = 0; kw < 7; kw++) {
        float v = w[(size_t)(co * 768 + ci) * 7 + kw];
        __nv_bfloat16 h = __float2bfloat16(v);
        __nv_bfloat16 l = __float2bfloat16(v - __bfloat162float(h));
        size_t base = ((size_t)kw * 256 + co) * 1536;
        dst[base + ci]       = h;
        dst[base + 768 + ci] = l;
    }
}

// w_hh [1024, 256] -> bf16 [1024, 512] = [hi | lo]
__global__ __launch_bounds__(256) void expand_whh(
    const float* __restrict__ w, __nv_bfloat16* __restrict__ dst)
{
    int idx = blockIdx.x * 256 + threadIdx.x;
    if (idx >= 1024 * 256) return;
    int n = idx >> 8, k = idx & 255;
    float v = w[idx];
    __nv_bfloat16 h = __float2bfloat16(v);
    dst[(size_t)n * 512 + k]       = h;
    dst[(size_t)n * 512 + 256 + k] = __float2bfloat16(v - __bfloat162float(h));
}

// zero h hi/lo ping buffer + c + hsum
__global__ __launch_bounds__(256) void lstm_init_kernel(
    __nv_bfloat16* hE, float* c, float* s)
{
    int idx = blockIdx.x * 256 + threadIdx.x;   // 512*256 = 131072
    c[idx] = 0.f; s[idx] = 0.f;
    ((u32*)hE)[idx] = 0u;                        // 262144 halves
}

// =====================================================================
// HMMA GEMM: C tile 128x128, BK=64-bf16 chunks, 8 warps (4m x 2n),
// warp tile 32m x 64n. mode 0: xproj. mode 1: conv1 (7 shifted, kw-inner).
// =====================================================================
#define KP 72
#define TILEH (128 * KP)
#define SMEMB (4 * TILEH * 2)   // 73728 B

__global__ __launch_bounds__(256) void gemm_mma(
    const __nv_bfloat16* __restrict__ A,
    const __nv_bfloat16* __restrict__ Bw,
    const float* __restrict__ bias0, const float* __restrict__ bias1,
    const float* __restrict__ biasC,
    float* __restrict__ out, int mode, int nchunks)
{
    extern __shared__ __align__(16) __nv_bfloat16 sm[];
    const int tid  = threadIdx.x;
    const int lane = tid & 31;
    const int warp = tid >> 5;
    const int wm = (warp & 3) * 32;
    const int wn = (warp >> 2) * 64;
    const int m0 = blockIdx.y * 128;
    const int n0 = blockIdx.x * 128;

    float acc[2][8][4];
#pragma unroll
    for (int mf = 0; mf < 2; mf++)
#pragma unroll
        for (int j = 0; j < 8; j++)
#pragma unroll
            for (int e = 0; e < 4; e++) acc[mf][j][e] = 0.f;

    auto stage = [&](int cc, int buf) {
        int kw = 0, c = cc;
        if (mode) { kw = cc % 7; c = cc / 7; }
        int acol = (c < 12) ? c * 64 : (c < 24) ? 768 + (c - 12) * 64 : (c - 24) * 64;
        int bcol = (c < 12) ? c * 64 : (c < 24) ? (c - 12) * 64 : 768 + (c - 24) * 64;
        const __nv_bfloat16* Bp = Bw + (mode ? (size_t)kw * 256 * 1536 : (size_t)0);
        u32 abase = smem_u32(sm + (size_t)buf * 2 * TILEH);
        u32 bbase = abase + TILEH * 2;
#pragma unroll
        for (int r = 0; r < 4; r++) {
            int idx = tid + r * 256;
            int row = idx >> 3, g = idx & 7;
            bool ok = true;
            const __nv_bfloat16* src;
            if (mode) {
                int p = row + kw - 3;
                ok = (p >= 0 && p < 128);
                src = A + (size_t)(m0 + (ok ? p : 0)) * 1536 + acol + g * 8;
            } else {
                src = A + (size_t)(m0 + row) * 1536 + acol + g * 8;
            }
            cpa16(abase + (row * KP + g * 8) * 2, src, ok);
        }
#pragma unroll
        for (int r = 0; r < 4; r++) {
            int idx = tid + r * 256;
            int row = idx >> 3, g = idx & 7;
            cpa16(bbase + (row * KP + g * 8) * 2,
                  Bp + (size_t)(n0 + row) * 1536 + bcol + g * 8, true);
        }
        CPA_COMMIT();
    };

    stage(0, 0);

    for (int cc = 0; cc < nchunks; cc++) {
        const int buf = cc & 1;
        CPA_WAIT0();
        __syncthreads();
        if (cc + 1 < nchunks) stage(cc + 1, 1 - buf);

        const __nv_bfloat16* Asb = sm + (size_t)buf * 2 * TILEH;
        const __nv_bfloat16* Bsb = Asb + TILEH;
        u32 abase = smem_u32(Asb);
        u32 bbase = smem_u32(Bsb);
#pragma unroll
        for (int k16 = 0; k16 < 4; k16++) {
            const int kh = k16 * 16;
            u32 a[2][4];
#pragma unroll
            for (int mf = 0; mf < 2; mf++) {
                u32 ad = abase +
                    ((wm + 16 * mf + (lane & 15)) * KP + kh + 8 * (lane >> 4)) * 2;
                ldmx4(a[mf][0], a[mf][1], a[mf][2], a[mf][3], ad);
            }
            u32 b[8][2];
            const int quad = lane >> 3, qr = lane & 7;
#pragma unroll
            for (int jj = 0; jj < 4; jj++) {
                u32 bd = bbase +
                    ((wn + 8 * (2 * jj + (quad >> 1)) + qr) * KP + kh + 8 * (quad & 1)) * 2;
                u32 r0, r1, r2, r3;
                ldmx4(r0, r1, r2, r3, bd);
                b[2 * jj][0] = r0; b[2 * jj][1] = r1;
                b[2 * jj + 1][0] = r2; b[2 * jj + 1][1] = r3;
            }
#pragma unroll
            for (int mf = 0; mf < 2; mf++)
#pragma unroll
                for (int j = 0; j < 8; j++)
                    mma16816(acc[mf][j], a[mf], b[j]);
        }
        __syncthreads();
    }

    if (mode == 0) {
#pragma unroll
        for (int mf = 0; mf < 2; mf++) {
            int r = wm + 16 * mf + (lane >> 2);
#pragma unroll
            for (int j = 0; j < 8; j++) {
                int n = n0 + wn + 8 * j + 2 * (lane & 3);
                float bs0 = bias0[n] + bias1[n];
                float bs1 = bias0[n + 1] + bias1[n + 1];
                float2 v0 = make_float2(acc[mf][j][0] + bs0, acc[mf][j][1] + bs1);
                float2 v1 = make_float2(acc[mf][j][2] + bs0, acc[mf][j][3] + bs1);
                *(float2*)&out[(size_t)(m0 + r) * G4 + n]     = v0;
                *(float2*)&out[(size_t)(m0 + r + 8) * G4 + n] = v1;
            }
        }
    } else {
        const int b = blockIdx.y;
        float* ob = out + (size_t)b * 256 * 64;
#pragma unroll
        for (int mf = 0; mf < 2; mf++) {
            int r = wm + 16 * mf + (lane >> 2);
#pragma unroll
            for (int j = 0; j < 8; j++) {
                int co = n0 + wn + 8 * j + 2 * (lane & 3);
                float d0 = acc[mf][j][0] + biasC[co];
                float d1 = acc[mf][j][1] + biasC[co + 1];
                float d2 = acc[mf][j][2] + biasC[co];
                float d3 = acc[mf][j][3] + biasC[co + 1];
                float o0 = __shfl_xor_sync(0xffffffffu, d0, 4);
                float o1 = __shfl_xor_sync(0xffffffffu, d1, 4);
                float o2 = __shfl_xor_sync(0xffffffffu, d2, 4);
                float o3 = __shfl_xor_sync(0xffffffffu, d3, 4);
                if (!(lane & 4)) {
                    int q0 = r >> 1, q1 = (r + 8) >> 1;
                    ob[(size_t)co * 64 + q0]       = fmaxf(fmaxf(d0, o0), 0.f);
                    ob[(size_t)(co + 1) * 64 + q0] = fmaxf(fmaxf(d1, o1), 0.f);
                    ob[(size_t)co * 64 + q1]       = fmaxf(fmaxf(d2, o2), 0.f);
                    ob[(size_t)(co + 1) * 64 + q1] = fmaxf(fmaxf(d3, o3), 0.f);
                }
            }
        }
    }
}

// =====================================================================
// HMMA LSTM step, SINGLE-STAGE: whole A (64x512) + B (128x512) staged
// with ONE cp.async group, then all 48 k16 iterations from resident
// smem (no further waits). Block owns (b0 = by*64, j0 = bx*32).
// smem (halves, pitch 520): B[0..128*520) A[128*520..192*520)
// exchange overlays A region. 199,680 B -> 1 CTA/SM, 64 blocks.
// =====================================================================
#define PB 520
#define LSM_A (128 * PB)
#define SMLS ((128 * PB + 64 * PB) * 2)   // 199680 B
#define PE 132

__global__ __launch_bounds__(256) void lstm_step_mma(
    const __nv_bfloat16* __restrict__ hprevE, __nv_bfloat16* __restrict__ hnextE,
    float* __restrict__ c, float* __restrict__ hsum,
    const __nv_bfloat16* __restrict__ whhE, const float* __restrict__ gx, int t)
{
    extern __shared__ __align__(16) __nv_bfloat16 sm[];
    const int tid  = threadIdx.x;
    const int lane = tid & 31;
    const int warp = tid >> 5;
    const int wm = (warp & 1) * 32;
    const int wn = (warp >> 1) * 32;
    const int j0 = blockIdx.x * 32;
    const int b0 = blockIdx.y * 64;

    const u32 smb = smem_u32(sm);
    const u32 bB = smb;
    const u32 bA = smb + LSM_A * 2;

    // ---- stage B (128 rows x 512 halves) + A (64 rows x 512) : ONE group ----
#pragma unroll
    for (int r = 0; r < 32; r++) {
        int idx = tid + r * 256;
        int row = idx >> 6, g = idx & 63;
        int wrow = (row >> 5) * 256 + j0 + (row & 31);   // n = gate*32 + jl
        cpa16(bB + (row * PB + g * 8) * 2,
              whhE + (size_t)wrow * 512 + g * 8, true);
    }
#pragma unroll
    for (int r = 0; r < 16; r++) {
        int idx = tid + r * 256;
        int row = idx >> 6, g = idx & 63;
        cpa16(bA + (row * PB + g * 8) * 2,
              hprevE + (size_t)(b0 + row) * 512 + g * 8, true);
    }
    CPA_COMMIT();

    float acc[2][4][4];
#pragma unroll
    for (int mf = 0; mf < 2; mf++)
#pragma unroll
        for (int j = 0; j < 4; j++)
#pragma unroll
            for (int e = 0; e < 4; e++) acc[mf][j][e] = 0.f;

    CPA_WAIT0();
    __syncthreads();

    // ---- 12 chunks x 4 k16, all from resident smem ----
#pragma unroll
    for (int cc = 0; cc < 12; cc++) {
        const int acol = (cc < 4) ? cc * 64 : (cc < 8) ? 256 + (cc - 4) * 64
                                                       : (cc - 8) * 64;
        const int bcol = (cc < 4) ? cc * 64 : (cc < 8) ? (cc - 4) * 64
                                                       : 256 + (cc - 8) * 64;
#pragma unroll
        for (int k16 = 0; k16 < 4; k16++) {
            const int kh = k16 * 16;
            u32 a[2][4];
#pragma unroll
            for (int mf = 0; mf < 2; mf++) {
                u32 ad = bA +
                    ((wm + 16 * mf + (lane & 15)) * PB + acol + kh +
                     8 * (lane >> 4)) * 2;
                ldmx4(a[mf][0], a[mf][1], a[mf][2], a[mf][3], ad);
            }
            u32 b[4][2];
            const int quad = lane >> 3, qr = lane & 7;
#pragma unroll
            for (int jj = 0; jj < 2; jj++) {
                u32 bd = bB +
                    ((wn + 8 * (2 * jj + (quad >> 1)) + qr) * PB + bcol + kh +
                     8 * (quad & 1)) * 2;
                u32 r0, r1, r2, r3;
                ldmx4(r0, r1, r2, r3, bd);
                b[2 * jj][0] = r0; b[2 * jj][1] = r1;
                b[2 * jj + 1][0] = r2; b[2 * jj + 1][1] = r3;
            }
#pragma unroll
            for (int mf = 0; mf < 2; mf++)
#pragma unroll
                for (int j = 0; j < 4; j++)
                    mma16816(acc[mf][j], a[mf], b[j]);
        }
    }
    __syncthreads();   // A-frags consumed; safe to overlay exchange

    // ---- exchange gates through smem (overlays A region) ----
    float* sE = (float*)(sm + LSM_A);
#pragma unroll
    for (int mf = 0; mf < 2; mf++) {
        int r = wm + 16 * mf + (lane >> 2);
#pragma unroll
        for (int j = 0; j < 4; j++) {
            int n = wn + 8 * j + 2 * (lane & 3);
            sE[r * PE + n]           = acc[mf][j][0];
            sE[r * PE + n + 1]       = acc[mf][j][1];
            sE[(r + 8) * PE + n]     = acc[mf][j][2];
            sE[(r + 8) * PE + n + 1] = acc[mf][j][3];
        }
    }
    __syncthreads();

    // ---- fused cell update: 64 b x 32 j = 2048 cells, 8 per thread ----
#pragma unroll
    for (int i = 0; i < 8; i++) {
        int idx = tid + i * 256;
        int bl = idx >> 5, jl = idx & 31;
        float gi = sE[bl * PE + jl];
        float gf = sE[bl * PE + 32 + jl];
        float gg = sE[bl * PE + 64 + jl];
        float go = sE[bl * PE + 96 + jl];
        int b = b0 + bl, j = j0 + jl;
        size_t gxo = ((size_t)b * LL + t) * G4 + j;
        float i_ = sigf(gi + gx[gxo]);
        float f_ = sigf(gf + gx[gxo + 256]);
        float g_ = tanhf(gg + gx[gxo + 512]);
        float o_ = sigf(go + gx[gxo + 768]);
        int ci = b * LHID + j;
        float cn = f_ * c[ci] + i_ * g_;
        c[ci] = cn;
        float hn = o_ * tanhf(cn);
        hsum[ci] += hn;
        __nv_bfloat16 hh = __float2bfloat16(hn);
        hnextE[(size_t)b * 512 + j]       = hh;
        hnextE[(size_t)b * 512 + 256 + j] = __float2bfloat16(hn - __bfloat162float(hh));
    }
}

// =====================================================================
// conv2/3/4 + mlp (unchanged — pass)
// =====================================================================
__global__ __launch_bounds__(256) void conv2_kernel(
    const float* __restrict__ in, const float* __restrict__ w,
    const float* __restrict__ bias, float* __restrict__ out)
{
    extern __shared__ float smf[];
    float* xs = smf;
    float* ws = smf + 32 * 69;
    const int b = blockIdx.x;
    const int tid = threadIdx.x;
    const int lane = tid & 31;
    const int cog  = tid >> 5;

    float acc[8][2];
#pragma unroll
    for (int j = 0; j < 8; j++) { acc[j][0] = 0.f; acc[j][1] = 0.f; }

    const float* ib = in + (size_t)b * 256 * 64;

    for (int ci0 = 0; ci0 < 256; ci0 += 32) {
        for (int idx = tid; idx < 32 * 68; idx += 256) {
            int cil = idx / 68, s = idx - cil * 68;
            int p = s - 2;
            xs[cil * 69 + s] =
                (p >= 0 && p < 64) ? ib[(size_t)(ci0 + cil) * 64 + p] : 0.f;
        }
        for (int idx = tid; idx < 64 * 160; idx += 256) {
            int col = idx / 160, r = idx - col * 160;
            ws[idx] = w[(size_t)col * (256 * 5) + ci0 * 5 + r];
        }
        __syncthreads();

        for (int ci = 0; ci < 32; ci++) {
            const float* xr = &xs[ci * 69 + lane];
            const float* wr = &ws[cog * 160 + ci * 5];
#pragma unroll
            for (int kw = 0; kw < 5; kw++) {
                float xv0 = xr[kw];
                float xv1 = xr[kw + 32];
#pragma unroll
                for (int j = 0; j < 8; j++) {
                    float wv = wr[j * (8 * 160) + kw];
                    acc[j][0] += wv * xv0;
                    acc[j][1] += wv * xv1;
                }
            }
        }
        __syncthreads();
    }

#pragma unroll
    for (int j = 0; j < 8; j++) {
        int co = cog + 8 * j;
        float bv = bias[co];
#pragma unroll
        for (int i = 0; i < 2; i++) {
            float v = acc[j][i] + bv;
            float o = __shfl_xor_sync(0xffffffffu, v, 1);
            float m = fmaxf(v, o);
            if (!(lane & 1)) {
                int q = (lane >> 1) + 16 * i;
                out[(size_t)b * 64 * 32 + (size_t)co * 32 + q] = fmaxf(m, 0.f);
            }
        }
    }
}

__global__ __launch_bounds__(256) void conv3_kernel(
    const float* __restrict__ in, const float* __restrict__ w,
    const float* __restrict__ bias, float* __restrict__ out)
{
    extern __shared__ float smf[];
    float* xs = smf;
    float* ws = smf + 64 * 37;
    const int b   = blockIdx.x;
    const int co0 = blockIdx.y * 128;
    const int tid = threadIdx.x;
    const int lane = tid & 31;
    const int cog  = tid >> 5;

    float acc[16];
#pragma unroll
    for (int j = 0; j < 16; j++) acc[j] = 0.f;

    const float* ib = in + (size_t)b * 64 * 32;

    for (int idx = tid; idx < 64 * 34; idx += 256) {
        int cil = idx / 34, s = idx - cil * 34;
        int p = s - 1;
        xs[cil * 37 + s] = (p >= 0 && p < 32) ? ib[(size_t)cil * 32 + p] : 0.f;
    }
    for (int idx = tid; idx < 128 * 192; idx += 256) {
        int col = idx / 192, r = idx - col * 192;
        ws[idx] = w[(size_t)(co0 + col) * 192 + r];
    }
    __syncthreads();

    for (int ci = 0; ci < 64; ci++) {
        const float* xr = &xs[ci * 37 + lane];
        float xv0 = xr[0], xv1 = xr[1], xv2 = xr[2];
        const float* wr = &ws[cog * 192 + ci * 3];
#pragma unroll
        for (int j = 0; j < 16; j++) {
            const float* wj = wr + j * (8 * 192);
            acc[j] += wj[0] * xv0 + wj[1] * xv1 + wj[2] * xv2;
        }
    }

#pragma unroll
    for (int j = 0; j < 16; j++) {
        int co = co0 + cog + 8 * j;
        float v = acc[j] + bias[co];
        float o = __shfl_xor_sync(0xffffffffu, v, 1);
        float m = fmaxf(v, o);
        if (!(lane & 1)) {
            int q = lane >> 1;
            out[(size_t)b * 256 * 16 + (size_t)co * 16 + q] = fmaxf(m, 0.f);
        }
    }
}

__global__ __launch_bounds__(256) void conv4_kernel(
    const float* __restrict__ in, const float* __restrict__ w,
    const float* __restrict__ bias, float* __restrict__ out)
{
    __shared__ float xsh[4096];
    __shared__ float wsh[4096];
    int b = blockIdx.x, tid = threadIdx.x;
    const float* ib = in + (size_t)b * 4096;
    for (int i = tid; i < 4096; i += 256) { xsh[i] = ib[i]; wsh[i] = w[i]; }
    __syncthreads();
    int co = tid >> 4, p = tid & 15;
    float acc = bias[co];
#pragma unroll 8
    for (int ci = 0; ci < 256; ci++)
        acc += xsh[ci * 16 + p] * wsh[co * 256 + ci];
    out[(size_t)b * 256 + co * 16 + p] = fmaxf(acc, 0.f);
}

__global__ __launch_bounds__(128) void mlp_kernel(
    const float* __restrict__ hsum, const float* __restrict__ feat,
    const float* __restrict__ w1, const float* __restrict__ b1,
    const float* __restrict__ w2, const float* __restrict__ b2,
    const float* __restrict__ w3, const float* __restrict__ b3,
    float* __restrict__ out)
{
    __shared__ float zin[512];
    __shared__ float z1[128];
    __shared__ float z2[32];
    int b = blockIdx.x, tid = threadIdx.x;
    for (int i = tid; i < 256; i += 128) {
        zin[i]       = hsum[(size_t)b * 256 + i] * (1.f / 128.f);
        zin[256 + i] = feat[(size_t)b * 256 + i];
    }
    __syncthreads();
    {
        const float* wr = w1 + (size_t)tid * 512;
        float acc = 0.f;
#pragma unroll 4
        for (int k = 0; k < 512; k += 4) {
            float4 wv = *(const float4*)(wr + k);
            float4 xv = *(const float4*)(&zin[k]);
            acc += wv.x * xv.x + wv.y * xv.y + wv.z * xv.z + wv.w * xv.w;
        }
        z1[tid] = fmaxf(acc + b1[tid], 0.f);
    }
    __syncthreads();
    if (tid < 32) {
        const float* wr = w2 + (size_t)tid * 128;
        float acc = 0.f;
#pragma unroll
        for (int k = 0; k < 128; k += 4) {
            float4 wv = *(const float4*)(wr + k);
            float4 xv = *(const float4*)(&z1[k]);
            acc += wv.x * xv.x + wv.y * xv.y + wv.z * xv.z + wv.w * xv.w;
        }
        z2[tid] = fmaxf(acc + b2[tid], 0.f);
    }
    __syncthreads();
    if (tid < 2) {
        const float* wr = w3 + (size_t)tid * 32;
        float acc = 0.f;
#pragma unroll
        for (int k = 0; k < 32; k++) acc += wr[k] * z2[k];
        out[(size_t)b * 2 + tid] = fmaxf(acc + b3[tid], 0.f);
    }
}

// =====================================================================
// host launcher
// =====================================================================
extern "C" void kernel_launch(void* const* d_in, const int* in_sizes, int n_in,
                              void* d_out, int out_size)
{
    const float* x    = (const float*)d_in[0];
    const float* w_ih = (const float*)d_in[1];
    const float* w_hh = (const float*)d_in[2];
    const float* b_ih = (const float*)d_in[3];
    const float* b_hh = (const float*)d_in[4];
    const float* c1w  = (const float*)d_in[5];
    const float* c1b  = (const float*)d_in[6];
    const float* c2w  = (const float*)d_in[7];
    const float* c2b  = (const float*)d_in[8];
    const float* c3w  = (const float*)d_in[9];
    const float* c3b  = (const float*)d_in[10];
    const float* c4w  = (const float*)d_in[11];
    const float* c4b  = (const float*)d_in[12];
    const float* f1w  = (const float*)d_in[13];
    const float* f1b  = (const float*)d_in[14];
    const float* f2w  = (const float*)d_in[15];
    const float* f2b  = (const float*)d_in[16];
    const float* f3w  = (const float*)d_in[17];
    const float* f3b  = (const float*)d_in[18];
    float* out = (float*)d_out;

    float *gatesx, *c, *hsum, *y1, *y2, *y3, *feat;
    __nv_bfloat16 *xE, *wihE, *wc1E, *whhE, *hEA, *hEB;
    cudaGetSymbolAddress((void**)&gatesx, g_gatesx);
    cudaGetSymbolAddress((void**)&xE,     g_xE);
    cudaGetSymbolAddress((void**)&wihE,   g_wihE);
    cudaGetSymbolAddress((void**)&wc1E,   g_wc1E);
    cudaGetSymbolAddress((void**)&whhE,   g_whhE);
    cudaGetSymbolAddress((void**)&hEA,    g_hEA);
    cudaGetSymbolAddress((void**)&hEB,    g_hEB);
    cudaGetSymbolAddress((void**)&c,      g_c);
    cudaGetSymbolAddress((void**)&hsum,   g_hsum);
    cudaGetSymbolAddress((void**)&y1,     g_y1);
    cudaGetSymbolAddress((void**)&y2,     g_y2);
    cudaGetSymbolAddress((void**)&y3,     g_y3);
    cudaGetSymbolAddress((void**)&feat,   g_feat);

    const int SM2 = (32 * 69 + 64 * 160) * 4;
    const int SM3 = (64 * 37 + 128 * 192) * 4;
    cudaFuncSetAttribute(conv2_kernel, cudaFuncAttributeMaxDynamicSharedMemorySize, SM2);
    cudaFuncSetAttribute(conv3_kernel, cudaFuncAttributeMaxDynamicSharedMemorySize, SM3);
    cudaFuncSetAttribute(gemm_mma, cudaFuncAttributeMaxDynamicSharedMemorySize, SMEMB);
    cudaFuncSetAttribute(lstm_step_mma, cudaFuncAttributeMaxDynamicSharedMemorySize, SMLS);

    // ---- bf16 hi/lo expansions ----
    expand_hl<<<(BB * LL * 192 + 255) / 256, 256>>>(x, xE, BB * LL * 192);
    expand_hl<<<(G4 * 192 + 255) / 256, 256>>>(w_ih, wihE, G4 * 192);
    expand_c1w<<<(256 * 768 + 255) / 256, 256>>>(c1w, wc1E);
    expand_whh<<<(1024 * 256 + 255) / 256, 256>>>(w_hh, whhE);

    // ---- conv1 via 7 accumulated HMMA GEMMs (kw-inner, 252 chunks) ----
    gemm_mma<<<dim3(2, BB), 256, SMEMB>>>(
        xE, wc1E, nullptr, nullptr, c1b, y1, 1, 7 * 36);

    // ---- rest of CNN ----
    conv2_kernel<<<BB, 256, SM2>>>(y1, c2w, c2b, y2);
    conv3_kernel<<<dim3(BB, 2), 256, SM3>>>(y2, c3w, c3b, y3);
    conv4_kernel<<<BB, 256>>>(y3, c4w, c4b, feat);

    // ---- input projection via HMMA (36 chunks) ----
    gemm_mma<<<dim3(G4 / 128, (BB * LL) / 128), 256, SMEMB>>>(
        xE, wihE, b_ih, b_hh, nullptr, gatesx, 0, 36);

    // ---- LSTM recurrence: single-stage HMMA step per launch ----
    lstm_init_kernel<<<BB, 256>>>(hEA, c, hsum);
    for (int t = 0; t < LL; t++) {
        const __nv_bfloat16* hp = (t & 1) ? hEB : hEA;
        __nv_bfloat16*       hn = (t & 1) ? hEA : hEB;
        lstm_step_mma<<<dim3(8, 8), 256, SMLS>>>(hp, hn, c, hsum, whhE, gatesx, t);
    }

    // ---- MLP head ----
    mlp_kernel<<<BB, 128>>>(hsum, feat, f1w, f1b, f2w, f2b, f3w, f3b, out);
}

// round 17
// speedup vs baseline: 1.8037x; 1.3120x over previous
#include <cuda_runtime.h>
#include <cuda_bf16.h>
#include <math.h>

// ---------------- problem dims ----------------
#define BB   512
#define LL   128
#define HH   768
#define LHID 256
#define G4   1024   // 4*LHID

typedef unsigned long long ull;
typedef unsigned int u32;

// ---------------- device scratch (no allocs allowed) ----------------
__device__ float g_gatesx[(size_t)BB * LL * G4];          // 256 MB
__device__ __nv_bfloat16 g_xE  [(size_t)BB * LL * 1536];  // [ah|al]
__device__ __nv_bfloat16 g_wihE[(size_t)G4 * 1536];       // [bh|bl]
__device__ __nv_bfloat16 g_wc1E[(size_t)7 * 256 * 1536];  // per-kw [bh|bl]
__device__ __nv_bfloat16 g_whhE[(size_t)G4 * 512];        // [bh|bl] over k=256
__device__ __nv_bfloat16 g_hEA [(size_t)BB * 512];        // h hi|lo ping
__device__ __nv_bfloat16 g_hEB [(size_t)BB * 512];        // h hi|lo pong
__device__ float g_c   [(size_t)BB * LHID];
__device__ float g_hsum[(size_t)BB * LHID];
__device__ float g_y1  [(size_t)BB * 256 * 64];
__device__ float g_y2  [(size_t)BB * 64 * 32];
__device__ float g_y3  [(size_t)BB * 256 * 16];
__device__ float g_feat[(size_t)BB * 256];

// ---------------- helpers ----------------
__device__ __forceinline__ float sigf(float x) { return 1.f / (1.f + expf(-x)); }
__device__ __forceinline__ u32 smem_u32(const void* p) {
    u32 a; asm("{ .reg .u64 t; cvta.to.shared.u64 t, %1; cvt.u32.u64 %0, t; }"
               : "=r"(a) : "l"(p));
    return a;
}
__device__ __forceinline__ void cpa16(u32 dst, const void* src, bool valid) {
    asm volatile("cp.async.cg.shared.global [%0], [%1], 16, %2;"
                 :: "r"(dst), "l"(src), "r"(valid ? 16 : 0));
}
#define CPA_COMMIT() asm volatile("cp.async.commit_group;" ::: "memory")
#define CPA_WAIT0()  asm volatile("cp.async.wait_group 0;" ::: "memory")

__device__ __forceinline__ void ldmx4(u32& a0, u32& a1, u32& a2, u32& a3, u32 addr) {
    asm volatile("ldmatrix.sync.aligned.m8n8.x4.shared.b16 {%0,%1,%2,%3}, [%4];"
                 : "=r"(a0), "=r"(a1), "=r"(a2), "=r"(a3) : "r"(addr));
}
__device__ __forceinline__ void mma16816(float* d, const u32* a, const u32* b) {
    asm volatile(
        "mma.sync.aligned.m16n8k16.row.col.f32.bf16.bf16.f32 "
        "{%0,%1,%2,%3}, {%4,%5,%6,%7}, {%8,%9}, {%0,%1,%2,%3};"
        : "+f"(d[0]), "+f"(d[1]), "+f"(d[2]), "+f"(d[3])
        : "r"(a[0]), "r"(a[1]), "r"(a[2]), "r"(a[3]), "r"(b[0]), "r"(b[1]));
}

// =====================================================================
// expand: fp32 [rows,768] -> bf16 [rows,1536] as [hi block | lo block]
// =====================================================================
__global__ __launch_bounds__(256) void expand_hl(
    const float* __restrict__ src, __nv_bfloat16* __restrict__ dst, int total4)
{
    int i = blockIdx.x * 256 + threadIdx.x;
    if (i >= total4) return;
    int r = i / 192, g = i - r * 192;
    float4 v = *(const float4*)(src + (size_t)r * 768 + g * 4);
    __nv_bfloat162 h01, h23, l01, l23;
    h01.x = __float2bfloat16(v.x); h01.y = __float2bfloat16(v.y);
    h23.x = __float2bfloat16(v.z); h23.y = __float2bfloat16(v.w);
    l01.x = __float2bfloat16(v.x - __bfloat162float(h01.x));
    l01.y = __float2bfloat16(v.y - __bfloat162float(h01.y));
    l23.x = __float2bfloat16(v.z - __bfloat162float(h23.x));
    l23.y = __float2bfloat16(v.w - __bfloat162float(h23.y));
    uint2 uh, ul;
    uh.x = *(u32*)&h01; uh.y = *(u32*)&h23;
    ul.x = *(u32*)&l01; ul.y = *(u32*)&l23;
    *(uint2*)(dst + (size_t)r * 1536 + g * 4)       = uh;
    *(uint2*)(dst + (size_t)r * 1536 + 768 + g * 4) = ul;
}

// conv1 weights [256, 768, 7] -> per-kw [256, 1536] as [hi|lo]
__global__ __launch_bounds__(256) void expand_c1w(
    const float* __restrict__ w, __nv_bfloat16* __restrict__ dst)
{
    int idx = blockIdx.x * 256 + threadIdx.x;
    if (idx >= 256 * 768) return;
    int co = idx / 768, ci = idx - co * 768;
#pragma unroll
    for (int kw = 0; kw < 7; kw++) {
        float v = w[(size_t)(co * 768 + ci) * 7 + kw];
        __nv_bfloat16 h = __float2bfloat16(v);
        __nv_bfloat16 l = __float2bfloat16(v - __bfloat162float(h));
        size_t base = ((size_t)kw * 256 + co) * 1536;
        dst[base + ci]       = h;
        dst[base + 768 + ci] = l;
    }
}

// w_hh [1024, 256] -> bf16 [1024, 512] = [hi | lo]
__global__ __launch_bounds__(256) void expand_whh(
    const float* __restrict__ w, __nv_bfloat16* __restrict__ dst)
{
    int idx = blockIdx.x * 256 + threadIdx.x;
    if (idx >= 1024 * 256) return;
    int n = idx >> 8, k = idx & 255;
    float v = w[idx];
    __nv_bfloat16 h = __float2bfloat16(v);
    dst[(size_t)n * 512 + k]       = h;
    dst[(size_t)n * 512 + 256 + k] = __float2bfloat16(v - __bfloat162float(h));
}

// zero h hi/lo ping buffer + c + hsum
__global__ __launch_bounds__(256) void lstm_init_kernel(
    __nv_bfloat16* hE, float* c, float* s)
{
    int idx = blockIdx.x * 256 + threadIdx.x;   // 512*256 = 131072
    c[idx] = 0.f; s[idx] = 0.f;
    ((u32*)hE)[idx] = 0u;                        // 262144 halves
}

// =====================================================================
// HMMA GEMM: C tile 128x128, BK=64-bf16 chunks, 8 warps (4m x 2n),
// warp tile 32m x 64n. mode 0: xproj. mode 1: conv1 (7 shifted, kw-inner).
// =====================================================================
#define KP 72
#define TILEH (128 * KP)
#define SMEMB (4 * TILEH * 2)   // 73728 B

__global__ __launch_bounds__(256) void gemm_mma(
    const __nv_bfloat16* __restrict__ A,
    const __nv_bfloat16* __restrict__ Bw,
    const float* __restrict__ bias0, const float* __restrict__ bias1,
    const float* __restrict__ biasC,
    float* __restrict__ out, int mode, int nchunks)
{
    extern __shared__ __align__(16) __nv_bfloat16 sm[];
    const int tid  = threadIdx.x;
    const int lane = tid & 31;
    const int warp = tid >> 5;
    const int wm = (warp & 3) * 32;
    const int wn = (warp >> 2) * 64;
    const int m0 = blockIdx.y * 128;
    const int n0 = blockIdx.x * 128;

    float acc[2][8][4];
#pragma unroll
    for (int mf = 0; mf < 2; mf++)
#pragma unroll
        for (int j = 0; j < 8; j++)
#pragma unroll
            for (int e = 0; e < 4; e++) acc[mf][j][e] = 0.f;

    auto stage = [&](int cc, int buf) {
        int kw = 0, c = cc;
        if (mode) { kw = cc % 7; c = cc / 7; }
        int acol = (c < 12) ? c * 64 : (c < 24) ? 768 + (c - 12) * 64 : (c - 24) * 64;
        int bcol = (c < 12) ? c * 64 : (c < 24) ? (c - 12) * 64 : 768 + (c - 24) * 64;
        const __nv_bfloat16* Bp = Bw + (mode ? (size_t)kw * 256 * 1536 : (size_t)0);
        u32 abase = smem_u32(sm + (size_t)buf * 2 * TILEH);
        u32 bbase = abase + TILEH * 2;
#pragma unroll
        for (int r = 0; r < 4; r++) {
            int idx = tid + r * 256;
            int row = idx >> 3, g = idx & 7;
            bool ok = true;
            const __nv_bfloat16* src;
            if (mode) {
                int p = row + kw - 3;
                ok = (p >= 0 && p < 128);
                src = A + (size_t)(m0 + (ok ? p : 0)) * 1536 + acol + g * 8;
            } else {
                src = A + (size_t)(m0 + row) * 1536 + acol + g * 8;
            }
            cpa16(abase + (row * KP + g * 8) * 2, src, ok);
        }
#pragma unroll
        for (int r = 0; r < 4; r++) {
            int idx = tid + r * 256;
            int row = idx >> 3, g = idx & 7;
            cpa16(bbase + (row * KP + g * 8) * 2,
                  Bp + (size_t)(n0 + row) * 1536 + bcol + g * 8, true);
        }
        CPA_COMMIT();
    };

    stage(0, 0);

    for (int cc = 0; cc < nchunks; cc++) {
        const int buf = cc & 1;
        CPA_WAIT0();
        __syncthreads();
        if (cc + 1 < nchunks) stage(cc + 1, 1 - buf);

        const __nv_bfloat16* Asb = sm + (size_t)buf * 2 * TILEH;
        const __nv_bfloat16* Bsb = Asb + TILEH;
        u32 abase = smem_u32(Asb);
        u32 bbase = smem_u32(Bsb);
#pragma unroll
        for (int k16 = 0; k16 < 4; k16++) {
            const int kh = k16 * 16;
            u32 a[2][4];
#pragma unroll
            for (int mf = 0; mf < 2; mf++) {
                u32 ad = abase +
                    ((wm + 16 * mf + (lane & 15)) * KP + kh + 8 * (lane >> 4)) * 2;
                ldmx4(a[mf][0], a[mf][1], a[mf][2], a[mf][3], ad);
            }
            u32 b[8][2];
            const int quad = lane >> 3, qr = lane & 7;
#pragma unroll
            for (int jj = 0; jj < 4; jj++) {
                u32 bd = bbase +
                    ((wn + 8 * (2 * jj + (quad >> 1)) + qr) * KP + kh + 8 * (quad & 1)) * 2;
                u32 r0, r1, r2, r3;
                ldmx4(r0, r1, r2, r3, bd);
                b[2 * jj][0] = r0; b[2 * jj][1] = r1;
                b[2 * jj + 1][0] = r2; b[2 * jj + 1][1] = r3;
            }
#pragma unroll
            for (int mf = 0; mf < 2; mf++)
#pragma unroll
                for (int j = 0; j < 8; j++)
                    mma16816(acc[mf][j], a[mf], b[j]);
        }
        __syncthreads();
    }

    if (mode == 0) {
#pragma unroll
        for (int mf = 0; mf < 2; mf++) {
            int r = wm + 16 * mf + (lane >> 2);
#pragma unroll
            for (int j = 0; j < 8; j++) {
                int n = n0 + wn + 8 * j + 2 * (lane & 3);
                float bs0 = bias0[n] + bias1[n];
                float bs1 = bias0[n + 1] + bias1[n + 1];
                float2 v0 = make_float2(acc[mf][j][0] + bs0, acc[mf][j][1] + bs1);
                float2 v1 = make_float2(acc[mf][j][2] + bs0, acc[mf][j][3] + bs1);
                *(float2*)&out[(size_t)(m0 + r) * G4 + n]     = v0;
                *(float2*)&out[(size_t)(m0 + r + 8) * G4 + n] = v1;
            }
        }
    } else {
        const int b = blockIdx.y;
        float* ob = out + (size_t)b * 256 * 64;
#pragma unroll
        for (int mf = 0; mf < 2; mf++) {
            int r = wm + 16 * mf + (lane >> 2);
#pragma unroll
            for (int j = 0; j < 8; j++) {
                int co = n0 + wn + 8 * j + 2 * (lane & 3);
                float d0 = acc[mf][j][0] + biasC[co];
                float d1 = acc[mf][j][1] + biasC[co + 1];
                float d2 = acc[mf][j][2] + biasC[co];
                float d3 = acc[mf][j][3] + biasC[co + 1];
                float o0 = __shfl_xor_sync(0xffffffffu, d0, 4);
                float o1 = __shfl_xor_sync(0xffffffffu, d1, 4);
                float o2 = __shfl_xor_sync(0xffffffffu, d2, 4);
                float o3 = __shfl_xor_sync(0xffffffffu, d3, 4);
                if (!(lane & 4)) {
                    int q0 = r >> 1, q1 = (r + 8) >> 1;
                    ob[(size_t)co * 64 + q0]       = fmaxf(fmaxf(d0, o0), 0.f);
                    ob[(size_t)(co + 1) * 64 + q0] = fmaxf(fmaxf(d1, o1), 0.f);
                    ob[(size_t)co * 64 + q1]       = fmaxf(fmaxf(d2, o2), 0.f);
                    ob[(size_t)(co + 1) * 64 + q1] = fmaxf(fmaxf(d3, o3), 0.f);
                }
            }
        }
    }
}

// =====================================================================
// HMMA LSTM step, SINGLE-STAGE, 128 blocks (16 b-tiles x 8 j-tiles).
// Block tile: 32 b x 32 j (x4 gates = 128 n). 8 warps (2m x 4n),
// warp tile 16m x 32n. A (32x512) + B (128x512) staged in ONE group.
// smem (halves, pitch 520): B[0..128*520) A[128*520..160*520)
// exchange (32x132 f32) overlays A region. 166,400 B -> 1 CTA/SM.
// =====================================================================
#define PB 520
#define LSM_A (128 * PB)
#define SMLS ((128 * PB + 32 * PB) * 2)   // 166400 B
#define PE 132

__global__ __launch_bounds__(256) void lstm_step_mma(
    const __nv_bfloat16* __restrict__ hprevE, __nv_bfloat16* __restrict__ hnextE,
    float* __restrict__ c, float* __restrict__ hsum,
    const __nv_bfloat16* __restrict__ whhE, const float* __restrict__ gx, int t)
{
    extern __shared__ __align__(16) __nv_bfloat16 sm[];
    const int tid  = threadIdx.x;
    const int lane = tid & 31;
    const int warp = tid >> 5;
    const int wm = (warp & 1) * 16;
    const int wn = (warp >> 1) * 32;
    const int j0 = blockIdx.x * 32;
    const int b0 = blockIdx.y * 32;

    const u32 smb = smem_u32(sm);
    const u32 bB = smb;
    const u32 bA = smb + LSM_A * 2;

    // ---- stage B (128 rows x 512 halves) + A (32 rows x 512) : ONE group ----
#pragma unroll
    for (int r = 0; r < 32; r++) {
        int idx = tid + r * 256;
        int row = idx >> 6, g = idx & 63;
        int wrow = (row >> 5) * 256 + j0 + (row & 31);   // n = gate*32 + jl
        cpa16(bB + (row * PB + g * 8) * 2,
              whhE + (size_t)wrow * 512 + g * 8, true);
    }
#pragma unroll
    for (int r = 0; r < 8; r++) {
        int idx = tid + r * 256;
        int row = idx >> 6, g = idx & 63;
        cpa16(bA + (row * PB + g * 8) * 2,
              hprevE + (size_t)(b0 + row) * 512 + g * 8, true);
    }
    CPA_COMMIT();

    float acc[4][4];
#pragma unroll
    for (int j = 0; j < 4; j++)
#pragma unroll
        for (int e = 0; e < 4; e++) acc[j][e] = 0.f;

    CPA_WAIT0();
    __syncthreads();

    // ---- 12 chunks x 4 k16, all from resident smem ----
#pragma unroll
    for (int cc = 0; cc < 12; cc++) {
        const int acol = (cc < 4) ? cc * 64 : (cc < 8) ? 256 + (cc - 4) * 64
                                                       : (cc - 8) * 64;
        const int bcol = (cc < 4) ? cc * 64 : (cc < 8) ? (cc - 4) * 64
                                                       : 256 + (cc - 8) * 64;
#pragma unroll
        for (int k16 = 0; k16 < 4; k16++) {
            const int kh = k16 * 16;
            u32 a[4];
            {
                u32 ad = bA +
                    ((wm + (lane & 15)) * PB + acol + kh + 8 * (lane >> 4)) * 2;
                ldmx4(a[0], a[1], a[2], a[3], ad);
            }
            u32 b[4][2];
            const int quad = lane >> 3, qr = lane & 7;
#pragma unroll
            for (int jj = 0; jj < 2; jj++) {
                u32 bd = bB +
                    ((wn + 8 * (2 * jj + (quad >> 1)) + qr) * PB + bcol + kh +
                     8 * (quad & 1)) * 2;
                u32 r0, r1, r2, r3;
                ldmx4(r0, r1, r2, r3, bd);
                b[2 * jj][0] = r0; b[2 * jj][1] = r1;
                b[2 * jj + 1][0] = r2; b[2 * jj + 1][1] = r3;
            }
#pragma unroll
            for (int j = 0; j < 4; j++)
                mma16816(acc[j], a, b[j]);
        }
    }
    __syncthreads();   // A-frags consumed; safe to overlay exchange

    // ---- exchange gates through smem (overlays A region) ----
    float* sE = (float*)(sm + LSM_A);
    {
        int r = wm + (lane >> 2);
#pragma unroll
        for (int j = 0; j < 4; j++) {
            int n = wn + 8 * j + 2 * (lane & 3);
            sE[r * PE + n]           = acc[j][0];
            sE[r * PE + n + 1]       = acc[j][1];
            sE[(r + 8) * PE + n]     = acc[j][2];
            sE[(r + 8) * PE + n + 1] = acc[j][3];
        }
    }
    __syncthreads();

    // ---- fused cell update: 32 b x 32 j = 1024 cells, 4 per thread ----
#pragma unroll
    for (int i = 0; i < 4; i++) {
        int idx = tid + i * 256;
        int bl = idx >> 5, jl = idx & 31;
        float gi = sE[bl * PE + jl];
        float gf = sE[bl * PE + 32 + jl];
        float gg = sE[bl * PE + 64 + jl];
        float go = sE[bl * PE + 96 + jl];
        int b = b0 + bl, j = j0 + jl;
        size_t gxo = ((size_t)b * LL + t) * G4 + j;
        float i_ = sigf(gi + gx[gxo]);
        float f_ = sigf(gf + gx[gxo + 256]);
        float g_ = tanhf(gg + gx[gxo + 512]);
        float o_ = sigf(go + gx[gxo + 768]);
        int ci = b * LHID + j;
        float cn = f_ * c[ci] + i_ * g_;
        c[ci] = cn;
        float hn = o_ * tanhf(cn);
        hsum[ci] += hn;
        __nv_bfloat16 hh = __float2bfloat16(hn);
        hnextE[(size_t)b * 512 + j]       = hh;
        hnextE[(size_t)b * 512 + 256 + j] = __float2bfloat16(hn - __bfloat162float(hh));
    }
}

// =====================================================================
// conv2/3/4 + mlp (unchanged — pass)
// =====================================================================
__global__ __launch_bounds__(256) void conv2_kernel(
    const float* __restrict__ in, const float* __restrict__ w,
    const float* __restrict__ bias, float* __restrict__ out)
{
    extern __shared__ float smf[];
    float* xs = smf;
    float* ws = smf + 32 * 69;
    const int b = blockIdx.x;
    const int tid = threadIdx.x;
    const int lane = tid & 31;
    const int cog  = tid >> 5;

    float acc[8][2];
#pragma unroll
    for (int j = 0; j < 8; j++) { acc[j][0] = 0.f; acc[j][1] = 0.f; }

    const float* ib = in + (size_t)b * 256 * 64;

    for (int ci0 = 0; ci0 < 256; ci0 += 32) {
        for (int idx = tid; idx < 32 * 68; idx += 256) {
            int cil = idx / 68, s = idx - cil * 68;
            int p = s - 2;
            xs[cil * 69 + s] =
                (p >= 0 && p < 64) ? ib[(size_t)(ci0 + cil) * 64 + p] : 0.f;
        }
        for (int idx = tid; idx < 64 * 160; idx += 256) {
            int col = idx / 160, r = idx - col * 160;
            ws[idx] = w[(size_t)col * (256 * 5) + ci0 * 5 + r];
        }
        __syncthreads();

        for (int ci = 0; ci < 32; ci++) {
            const float* xr = &xs[ci * 69 + lane];
            const float* wr = &ws[cog * 160 + ci * 5];
#pragma unroll
            for (int kw = 0; kw < 5; kw++) {
                float xv0 = xr[kw];
                float xv1 = xr[kw + 32];
#pragma unroll
                for (int j = 0; j < 8; j++) {
                    float wv = wr[j * (8 * 160) + kw];
                    acc[j][0] += wv * xv0;
                    acc[j][1] += wv * xv1;
                }
            }
        }
        __syncthreads();
    }

#pragma unroll
    for (int j = 0; j < 8; j++) {
        int co = cog + 8 * j;
        float bv = bias[co];
#pragma unroll
        for (int i = 0; i < 2; i++) {
            float v = acc[j][i] + bv;
            float o = __shfl_xor_sync(0xffffffffu, v, 1);
            float m = fmaxf(v, o);
            if (!(lane & 1)) {
                int q = (lane >> 1) + 16 * i;
                out[(size_t)b * 64 * 32 + (size_t)co * 32 + q] = fmaxf(m, 0.f);
            }
        }
    }
}

__global__ __launch_bounds__(256) void conv3_kernel(
    const float* __restrict__ in, const float* __restrict__ w,
    const float* __restrict__ bias, float* __restrict__ out)
{
    extern __shared__ float smf[];
    float* xs = smf;
    float* ws = smf + 64 * 37;
    const int b   = blockIdx.x;
    const int co0 = blockIdx.y * 128;
    const int tid = threadIdx.x;
    const int lane = tid & 31;
    const int cog  = tid >> 5;

    float acc[16];
#pragma unroll
    for (int j = 0; j < 16; j++) acc[j] = 0.f;

    const float* ib = in + (size_t)b * 64 * 32;

    for (int idx = tid; idx < 64 * 34; idx += 256) {
        int cil = idx / 34, s = idx - cil * 34;
        int p = s - 1;
        xs[cil * 37 + s] = (p >= 0 && p < 32) ? ib[(size_t)cil * 32 + p] : 0.f;
    }
    for (int idx = tid; idx < 128 * 192; idx += 256) {
        int col = idx / 192, r = idx - col * 192;
        ws[idx] = w[(size_t)(co0 + col) * 192 + r];
    }
    __syncthreads();

    for (int ci = 0; ci < 64; ci++) {
        const float* xr = &xs[ci * 37 + lane];
        float xv0 = xr[0], xv1 = xr[1], xv2 = xr[2];
        const float* wr = &ws[cog * 192 + ci * 3];
#pragma unroll
        for (int j = 0; j < 16; j++) {
            const float* wj = wr + j * (8 * 192);
            acc[j] += wj[0] * xv0 + wj[1] * xv1 + wj[2] * xv2;
        }
    }

#pragma unroll
    for (int j = 0; j < 16; j++) {
        int co = co0 + cog + 8 * j;
        float v = acc[j] + bias[co];
        float o = __shfl_xor_sync(0xffffffffu, v, 1);
        float m = fmaxf(v, o);
        if (!(lane & 1)) {
            int q = lane >> 1;
            out[(size_t)b * 256 * 16 + (size_t)co * 16 + q] = fmaxf(m, 0.f);
        }
    }
}

__global__ __launch_bounds__(256) void conv4_kernel(
    const float* __restrict__ in, const float* __restrict__ w,
    const float* __restrict__ bias, float* __restrict__ out)
{
    __shared__ float xsh[4096];
    __shared__ float wsh[4096];
    int b = blockIdx.x, tid = threadIdx.x;
    const float* ib = in + (size_t)b * 4096;
    for (int i = tid; i < 4096; i += 256) { xsh[i] = ib[i]; wsh[i] = w[i]; }
    __syncthreads();
    int co = tid >> 4, p = tid & 15;
    float acc = bias[co];
#pragma unroll 8
    for (int ci = 0; ci < 256; ci++)
        acc += xsh[ci * 16 + p] * wsh[co * 256 + ci];
    out[(size_t)b * 256 + co * 16 + p] = fmaxf(acc, 0.f);
}

__global__ __launch_bounds__(128) void mlp_kernel(
    const float* __restrict__ hsum, const float* __restrict__ feat,
    const float* __restrict__ w1, const float* __restrict__ b1,
    const float* __restrict__ w2, const float* __restrict__ b2,
    const float* __restrict__ w3, const float* __restrict__ b3,
    float* __restrict__ out)
{
    __shared__ float zin[512];
    __shared__ float z1[128];
    __shared__ float z2[32];
    int b = blockIdx.x, tid = threadIdx.x;
    for (int i = tid; i < 256; i += 128) {
        zin[i]       = hsum[(size_t)b * 256 + i] * (1.f / 128.f);
        zin[256 + i] = feat[(size_t)b * 256 + i];
    }
    __syncthreads();
    {
        const float* wr = w1 + (size_t)tid * 512;
        float acc = 0.f;
#pragma unroll 4
        for (int k = 0; k < 512; k += 4) {
            float4 wv = *(const float4*)(wr + k);
            float4 xv = *(const float4*)(&zin[k]);
            acc += wv.x * xv.x + wv.y * xv.y + wv.z * xv.z + wv.w * xv.w;
        }
        z1[tid] = fmaxf(acc + b1[tid], 0.f);
    }
    __syncthreads();
    if (tid < 32) {
        const float* wr = w2 + (size_t)tid * 128;
        float acc = 0.f;
#pragma unroll
        for (int k = 0; k < 128; k += 4) {
            float4 wv = *(const float4*)(wr + k);
            float4 xv = *(const float4*)(&z1[k]);
            acc += wv.x * xv.x + wv.y * xv.y + wv.z * xv.z + wv.w * xv.w;
        }
        z2[tid] = fmaxf(acc + b2[tid], 0.f);
    }
    __syncthreads();
    if (tid < 2) {
        const float* wr = w3 + (size_t)tid * 32;
        float acc = 0.f;
#pragma unroll
        for (int k = 0; k < 32; k++) acc += wr[k] * z2[k];
        out[(size_t)b * 2 + tid] = fmaxf(acc + b3[tid], 0.f);
    }
}

// =====================================================================
// host launcher — fork/join stream overlap of CNN branch vs LSTM branch
// =====================================================================
extern "C" void kernel_launch(void* const* d_in, const int* in_sizes, int n_in,
                              void* d_out, int out_size)
{
    const float* x    = (const float*)d_in[0];
    const float* w_ih = (const float*)d_in[1];
    const float* w_hh = (const float*)d_in[2];
    const float* b_ih = (const float*)d_in[3];
    const float* b_hh = (const float*)d_in[4];
    const float* c1w  = (const float*)d_in[5];
    const float* c1b  = (const float*)d_in[6];
    const float* c2w  = (const float*)d_in[7];
    const float* c2b  = (const float*)d_in[8];
    const float* c3w  = (const float*)d_in[9];
    const float* c3b  = (const float*)d_in[10];
    const float* c4w  = (const float*)d_in[11];
    const float* c4b  = (const float*)d_in[12];
    const float* f1w  = (const float*)d_in[13];
    const float* f1b  = (const float*)d_in[14];
    const float* f2w  = (const float*)d_in[15];
    const float* f2b  = (const float*)d_in[16];
    const float* f3w  = (const float*)d_in[17];
    const float* f3b  = (const float*)d_in[18];
    float* out = (float*)d_out;

    float *gatesx, *c, *hsum, *y1, *y2, *y3, *feat;
    __nv_bfloat16 *xE, *wihE, *wc1E, *whhE, *hEA, *hEB;
    cudaGetSymbolAddress((void**)&gatesx, g_gatesx);
    cudaGetSymbolAddress((void**)&xE,     g_xE);
    cudaGetSymbolAddress((void**)&wihE,   g_wihE);
    cudaGetSymbolAddress((void**)&wc1E,   g_wc1E);
    cudaGetSymbolAddress((void**)&whhE,   g_whhE);
    cudaGetSymbolAddress((void**)&hEA,    g_hEA);
    cudaGetSymbolAddress((void**)&hEB,    g_hEB);
    cudaGetSymbolAddress((void**)&c,      g_c);
    cudaGetSymbolAddress((void**)&hsum,   g_hsum);
    cudaGetSymbolAddress((void**)&y1,     g_y1);
    cudaGetSymbolAddress((void**)&y2,     g_y2);
    cudaGetSymbolAddress((void**)&y3,     g_y3);
    cudaGetSymbolAddress((void**)&feat,   g_feat);

    // host-side infra, created once (no device memory involved)
    static cudaStream_t s2 = nullptr;
    static cudaEvent_t ev1 = nullptr, ev2 = nullptr;
    if (!s2) {
        cudaStreamCreateWithFlags(&s2, cudaStreamNonBlocking);
        cudaEventCreateWithFlags(&ev1, cudaEventDisableTiming);
        cudaEventCreateWithFlags(&ev2, cudaEventDisableTiming);
    }

    const int SM2 = (32 * 69 + 64 * 160) * 4;
    const int SM3 = (64 * 37 + 128 * 192) * 4;
    cudaFuncSetAttribute(conv2_kernel, cudaFuncAttributeMaxDynamicSharedMemorySize, SM2);
    cudaFuncSetAttribute(conv3_kernel, cudaFuncAttributeMaxDynamicSharedMemorySize, SM3);
    cudaFuncSetAttribute(gemm_mma, cudaFuncAttributeMaxDynamicSharedMemorySize, SMEMB);
    cudaFuncSetAttribute(lstm_step_mma, cudaFuncAttributeMaxDynamicSharedMemorySize, SMLS);

    // ---- shared prerequisite: xE ----
    expand_hl<<<(BB * LL * 192 + 255) / 256, 256>>>(x, xE, BB * LL * 192);

    // ---- fork: CNN branch on s2 ----
    cudaEventRecord(ev1, 0);
    cudaStreamWaitEvent(s2, ev1, 0);
    expand_c1w<<<(256 * 768 + 255) / 256, 256, 0, s2>>>(c1w, wc1E);
    gemm_mma<<<dim3(2, BB), 256, SMEMB, s2>>>(
        xE, wc1E, nullptr, nullptr, c1b, y1, 1, 7 * 36);
    conv2_kernel<<<BB, 256, SM2, s2>>>(y1, c2w, c2b, y2);
    conv3_kernel<<<dim3(BB, 2), 256, SM3, s2>>>(y2, c3w, c3b, y3);
    conv4_kernel<<<BB, 256, 0, s2>>>(y3, c4w, c4b, feat);
    cudaEventRecord(ev2, s2);

    // ---- LSTM branch on main stream ----
    expand_hl<<<(G4 * 192 + 255) / 256, 256>>>(w_ih, wihE, G4 * 192);
    expand_whh<<<(1024 * 256 + 255) / 256, 256>>>(w_hh, whhE);
    gemm_mma<<<dim3(G4 / 128, (BB * LL) / 128), 256, SMEMB>>>(
        xE, wihE, b_ih, b_hh, nullptr, gatesx, 0, 36);
    lstm_init_kernel<<<BB, 256>>>(hEA, c, hsum);
    for (int t = 0; t < LL; t++) {
        const __nv_bfloat16* hp = (t & 1) ? hEB : hEA;
        __nv_bfloat16*       hn = (t & 1) ? hEA : hEB;
        lstm_step_mma<<<dim3(8, 16), 256, SMLS>>>(hp, hn, c, hsum, whhE, gatesx, t);
    }

    // ---- join + head ----
    cudaStreamWaitEvent(0, ev2, 0);
    mlp_kernel<<<BB, 128>>>(hsum, feat, f1w, f1b, f2w, f2b, f3w, f3b, out);
}